// round 15
// baseline (speedup 1.0000x reference)
#include <cuda_runtime.h>
#include <cooperative_groups.h>
#include <cstdint>

namespace cg = cooperative_groups;

#define MARGIN 1.0f
#define MAX_TRIALS 50
#define BLK 256
#define EPB 1024                           // elements per block
#define MAX_B (1 << 20)
#define MAX_NB (MAX_B / EPB)               // 1024

// Scratch (no allocations allowed in kernel_launch)
__device__ float g_neg_score[MAX_B];   // scores of label-0 examples, stable order
__device__ int   g_blockcnt[MAX_NB];
__device__ float g_extra;
__device__ float g_harm[MAX_TRIALS];

// ---------------- Threefry-2x32 (exact JAX partitionable semantics) --------
__device__ __forceinline__ uint32_t rotl32(uint32_t x, int d) {
    return __funnelshift_l(x, x, d);
}

__device__ __forceinline__ uint32_t jax_random_bits32(uint32_t j) {
    const uint32_t k0 = 0u, k1 = 42u;
    const uint32_t ks2 = k0 ^ k1 ^ 0x1BD11BDAu;
    uint32_t x0 = 0u + k0;          // c0 = hi32(j) = 0
    uint32_t x1 = j + k1;           // c1 = lo32(j)
    const int R0[4] = {13, 15, 26, 6};
    const int R1[4] = {17, 29, 16, 24};
#pragma unroll
    for (int i = 0; i < 4; i++) { x0 += x1; x1 = rotl32(x1, R0[i]); x1 ^= x0; }
    x0 += k1;  x1 += ks2 + 1u;
#pragma unroll
    for (int i = 0; i < 4; i++) { x0 += x1; x1 = rotl32(x1, R1[i]); x1 ^= x0; }
    x0 += ks2; x1 += k0 + 2u;
#pragma unroll
    for (int i = 0; i < 4; i++) { x0 += x1; x1 = rotl32(x1, R0[i]); x1 ^= x0; }
    x0 += k0;  x1 += k1 + 3u;
#pragma unroll
    for (int i = 0; i < 4; i++) { x0 += x1; x1 = rotl32(x1, R1[i]); x1 ^= x0; }
    x0 += k1;  x1 += ks2 + 4u;
#pragma unroll
    for (int i = 0; i < 4; i++) { x0 += x1; x1 = rotl32(x1, R0[i]); x1 ^= x0; }
    x0 += ks2; x1 += k0 + 5u;
    return x0 ^ x1;
}

__device__ __forceinline__ float bits_to_uniform(uint32_t bits) {
    return __uint_as_float((bits >> 9) | 0x3f800000u) - 1.0f;
}

__device__ __forceinline__ float sample_neg(uint32_t j, float nnf, int num_neg) {
    float u = bits_to_uniform(jax_random_bits32(j));
    int idx = (int)(u * nnf);
    idx = min(max(idx, 0), num_neg - 1);
    return __ldg(&g_neg_score[idx]);
}

__device__ __forceinline__ float warp_weight(int t) {
    int rank = max(1, MAX_TRIALS / (t + 1));
    return __ldg(&g_harm[rank - 1]);
}

// ---------------- ONE cooperative kernel -----------------------------------
__global__ __launch_bounds__(BLK, 8)
void everything_kernel(const int* __restrict__ labels,
                       const float* __restrict__ scores,
                       float* __restrict__ out, int B, int nb) {
    cg::grid_group grid = cg::this_grid();
    __shared__ int   wtot[BLK / 32];
    __shared__ int   woff[BLK / 32];
    __shared__ int   redi[BLK];
    __shared__ int   redt[BLK];
    __shared__ uint32_t q1_jb[1024];
    __shared__ float    q1_s[1024];
    __shared__ uint32_t q2_jb[512];
    __shared__ float    q2_s[512];
    __shared__ uint32_t q3_jb[256];
    __shared__ float    q3_s[256];
    __shared__ int q1n, q2n, q3n, take1, take2;
    __shared__ float red[BLK];
    __shared__ int s_exc, s_tot;

    int bid = blockIdx.x;
    int tid = threadIdx.x;
    int lane = tid & 31;
    int w = tid >> 5;

    // ---------- Phase A: load once, per-block zero count -------------------
    int e0 = (bid * BLK + tid) * 4;
    int   lab[4];
    float sc[4];
    if (e0 + 3 < B) {
        int4   lv = __ldg((const int4*)(labels + e0));
        float4 sv = __ldg((const float4*)(scores + e0));
        lab[0] = lv.x; lab[1] = lv.y; lab[2] = lv.z; lab[3] = lv.w;
        sc[0] = sv.x; sc[1] = sv.y; sc[2] = sv.z; sc[3] = sv.w;
    } else {
#pragma unroll
        for (int k = 0; k < 4; k++) {
            lab[k] = (e0 + k < B) ? labels[e0 + k] : 1;
            sc[k]  = (e0 + k < B) ? scores[e0 + k] : 0.0f;
        }
    }
    int f[4], c = 0;
#pragma unroll
    for (int k = 0; k < 4; k++) { f[k] = (e0 + k < B && lab[k] == 0) ? 1 : 0; c += f[k]; }
    int isp = 0;
#pragma unroll
    for (int k = 0; k < 4; k++) if (e0 + k < B && lab[k] == 1) isp |= (1 << k);

    int incl = c;
#pragma unroll
    for (int off = 1; off < 32; off <<= 1) {
        int y = __shfl_up_sync(0xffffffffu, incl, off);
        if (lane >= off) incl += y;
    }
    int thr_exc = incl - c;
    if (lane == 31) wtot[w] = incl;
    __syncthreads();
    if (tid == 0) {
        int r = 0;
#pragma unroll
        for (int k = 0; k < BLK / 32; k++) { int t = wtot[k]; woff[k] = r; r += t; }
        g_blockcnt[bid] = r;
        q1n = 0; q2n = 0; q3n = 0; take1 = 0; take2 = 0;
        if (bid == 0) {
            g_extra = 0.0f;
            float h = 0.0f;
#pragma unroll
            for (int j = 1; j <= MAX_TRIALS; j++) {
                h += __fdiv_rn(1.0f, (float)j);
                g_harm[j - 1] = h;
            }
        }
    }
    grid.sync();

    // ---------- Phase B: block prefix + total, scatter NEGATIVES only ------
    {
        int pref = 0, tot = 0;
        for (int j = tid; j < nb; j += BLK) {
            int v = g_blockcnt[j];
            tot += v;
            if (j < bid) pref += v;
        }
        redi[tid] = pref;
        redt[tid] = tot;
        __syncthreads();
        for (int off = BLK / 2; off > 0; off >>= 1) {
            if (tid < off) { redi[tid] += redi[tid + off]; redt[tid] += redt[tid + off]; }
            __syncthreads();
        }
        if (tid == 0) { s_exc = redi[0]; s_tot = redt[0]; }
        __syncthreads();

        int neg_before = s_exc + woff[w] + thr_exc;
#pragma unroll
        for (int k = 0; k < 4; k++) {
            if (f[k]) g_neg_score[neg_before] = sc[k];
            neg_before += f[k];
        }
    }
    int num_neg = s_tot;
    int num_pos = B - num_neg;
    grid.sync();

    // ---------- Phase C: WARP loss on register-held positives --------------
    float nnf = (float)num_neg;
    float acc = 0.0f;

    if (num_neg > 0) {
        // trial 0, batched across this thread's positives
        float ns0[4];
#pragma unroll
        for (int k = 0; k < 4; k++)
            if (isp & (1 << k))
                ns0[k] = sample_neg((uint32_t)(e0 + k) * (uint32_t)MAX_TRIALS,
                                    nnf, num_neg);
#pragma unroll
        for (int k = 0; k < 4; k++) {
            if (isp & (1 << k)) {
                float s = sc[k];
                if (ns0[k] + MARGIN > s) {
                    acc += __ldg(&g_harm[MAX_TRIALS - 1]) *
                           fmaxf(MARGIN - (s - ns0[k]), 0.0f);
                } else {
                    int h = atomicAdd(&q1n, 1);
                    q1_jb[h] = (uint32_t)(e0 + k) * (uint32_t)MAX_TRIALS;
                    q1_s[h]  = s;
                }
            }
        }
    }
    __syncthreads();

    // trials 1..4 — 8 survivors/warp, 4 lanes per survivor
    if (num_neg > 0) {
        int n1 = q1n;
        int sub = lane & 3;
        int t = 1 + sub;
        while (true) {
            int b;
            if (lane == 0) b = atomicAdd(&take1, 8);
            b = __shfl_sync(0xffffffffu, b, 0);
            if (b >= n1) break;
            int nrem = n1 - b;
            int sid = lane >> 2;
            bool active = (sid < nrem);
            int qi = b + (active ? sid : 0);
            uint32_t jb = q1_jb[qi];
            float s = q1_s[qi];
            float ns = active ? sample_neg(jb + (uint32_t)t, nnf, num_neg) : 0.0f;
            bool viol = active && (ns + MARGIN > s);
            unsigned m = __ballot_sync(0xffffffffu, viol);
            unsigned nib = (m >> ((lane >> 2) * 4)) & 0xFu;
            if (viol && ((nib & ((1u << sub) - 1u)) == 0u)) {
                acc += warp_weight(t) * fmaxf(MARGIN - (s - ns), 0.0f);
            }
            if (active && sub == 0 && nib == 0u) {
                int h = atomicAdd(&q2n, 1);
                if (h < 512) { q2_jb[h] = jb; q2_s[h] = s; }
            }
        }
    }
    __syncthreads();

    // trials 5..8 — same pattern on q2, heavies -> q3
    if (num_neg > 0) {
        int n2 = min(q2n, 512);
        int sub = lane & 3;
        int t = 5 + sub;
        while (true) {
            int b;
            if (lane == 0) b = atomicAdd(&take2, 8);
            b = __shfl_sync(0xffffffffu, b, 0);
            if (b >= n2) break;
            int nrem = n2 - b;
            int sid = lane >> 2;
            bool active = (sid < nrem);
            int qi = b + (active ? sid : 0);
            uint32_t jb = q2_jb[qi];
            float s = q2_s[qi];
            float ns = active ? sample_neg(jb + (uint32_t)t, nnf, num_neg) : 0.0f;
            bool viol = active && (ns + MARGIN > s);
            unsigned m = __ballot_sync(0xffffffffu, viol);
            unsigned nib = (m >> ((lane >> 2) * 4)) & 0xFu;
            if (viol && ((nib & ((1u << sub) - 1u)) == 0u)) {
                acc += warp_weight(t) * fmaxf(MARGIN - (s - ns), 0.0f);
            }
            if (active && sub == 0 && nib == 0u) {
                int h = atomicAdd(&q3n, 1);
                if (h < 256) { q3_jb[h] = jb; q3_s[h] = s; }
            }
        }
    }
    __syncthreads();

    // heavies — one warp per item, lanes = trials 9..40, then 41..49
    if (num_neg > 0) {
        int n3 = min(q3n, 256);
        int wd = tid >> 5;
        int nw = BLK >> 5;
        for (int h = wd; h < n3; h += nw) {
            uint32_t jb = q3_jb[h];
            float s = q3_s[h];
            int t1 = 9 + lane;
            float ns1 = sample_neg(jb + (uint32_t)t1, nnf, num_neg);
            unsigned m1 = __ballot_sync(0xffffffffu, ns1 + MARGIN > s);
            int hit_t = -1;
            float hit_ns = 0.0f;
            if (m1) {
                int lead = __ffs(m1) - 1;
                hit_t = 9 + lead;
                hit_ns = __shfl_sync(0xffffffffu, ns1, lead);
            } else {
                int t2 = 41 + lane;
                bool act = (t2 < MAX_TRIALS);
                float ns2 = act ? sample_neg(jb + (uint32_t)t2, nnf, num_neg) : 0.0f;
                unsigned m2 = __ballot_sync(0xffffffffu, act && (ns2 + MARGIN > s));
                if (m2) {
                    int lead = __ffs(m2) - 1;
                    hit_t = 41 + lead;
                    hit_ns = __shfl_sync(0xffffffffu, ns2, lead);
                }
            }
            if (lane == 0 && hit_t >= 0) {
                acc += warp_weight(hit_t) * fmaxf(MARGIN - (s - hit_ns), 0.0f);
            }
        }
    }

    // block reduction -> one global atomic per block
    red[tid] = acc;
    __syncthreads();
    for (int off = BLK / 2; off > 0; off >>= 1) {
        if (tid < off) red[tid] += red[tid + off];
        __syncthreads();
    }
    if (tid == 0 && red[0] != 0.0f) atomicAdd(&g_extra, red[0]);
    grid.sync();

    if (bid == 0 && tid == 0) {
        out[0] = (num_neg > 0 && num_pos > 0) ? g_extra / (float)num_pos : 0.0f;
    }
}

extern "C" void kernel_launch(void* const* d_in, const int* in_sizes, int n_in,
                              void* d_out, int out_size) {
    const float* scores = (const float*)d_in[0];
    const int*   labels = (const int*)d_in[1];
    float* out = (float*)d_out;
    int B  = in_sizes[0];
    int nb = (B + EPB - 1) / EPB;

    void* args[] = { (void*)&labels, (void*)&scores, (void*)&out,
                     (void*)&B, (void*)&nb };
    cudaLaunchCooperativeKernel((void*)everything_kernel,
                                dim3(nb), dim3(BLK), args, 0, 0);
}